// round 1
// baseline (speedup 1.0000x reference)
#include <cuda_runtime.h>
#include <cstdint>

// Problem constants (fixed shapes for this problem)
#define BB 2
#define VV 5
#define CC 16
#define HH 512
#define WW 640
#define NN 131072
#define BV (BB*VV)
#define HW (HH*WW)

// Transposed feature maps: (BV, H, W, C) so all 16 channels of a pixel are
// contiguous (64B). 210 MB static scratch (uninitialized -> no cubin bloat).
__device__ float g_fmT[(size_t)BV * HW * CC];

// ---------------------------------------------------------------------------
// Kernel 1: transpose (BV, C, H, W) -> (BV, H, W, C)
// Each thread handles one pixel: 16 coalesced strided reads (per-c, warp reads
// 128B contiguous), 4 float4 writes (warp covers a contiguous 2KB span).
// ---------------------------------------------------------------------------
__global__ void fgf_transpose(const float* __restrict__ fm) {
    int pix = blockIdx.x * blockDim.x + threadIdx.x;
    if (pix >= BV * HW) return;
    int bv = pix / HW;
    int r  = pix - bv * HW;
    const float* src = fm + (size_t)bv * CC * HW + r;
    float v[CC];
#pragma unroll
    for (int c = 0; c < CC; c++) v[c] = src[(size_t)c * HW];
    float4* dst = reinterpret_cast<float4*>(g_fmT + ((size_t)bv * HW + r) * CC);
#pragma unroll
    for (int q = 0; q < 4; q++)
        dst[q] = make_float4(v[4*q], v[4*q+1], v[4*q+2], v[4*q+3]);
}

// ---------------------------------------------------------------------------
// Kernel 2: project + 5x bilinear sample + finite-diff gradients
// ---------------------------------------------------------------------------
struct Samp {
    int   o0, o1, o2, o3;     // pixel offsets * C (element offset into fmT)
    float w0, w1, w2, w3;     // bilinear weights (0 if out of bounds)
};

__device__ __forceinline__ Samp make_samp(float gx, float gy) {
    float ix = ((gx + 1.0f) * (float)WW - 1.0f) * 0.5f;
    float iy = ((gy + 1.0f) * (float)HH - 1.0f) * 0.5f;
    float x0f = floorf(ix), y0f = floorf(iy);
    float wx1 = ix - x0f, wy1 = iy - y0f;
    float wx0 = 1.0f - wx1, wy0 = 1.0f - wy1;
    int x0 = (int)x0f, y0 = (int)y0f;
    int x1 = x0 + 1,  y1 = y0 + 1;

    bool vx0 = (x0 >= 0) && (x0 <= WW - 1);
    bool vx1 = (x1 >= 0) && (x1 <= WW - 1);
    bool vy0 = (y0 >= 0) && (y0 <= HH - 1);
    bool vy1 = (y1 >= 0) && (y1 <= HH - 1);

    int cx0 = min(max(x0, 0), WW - 1);
    int cx1 = min(max(x1, 0), WW - 1);
    int cy0 = min(max(y0, 0), HH - 1);
    int cy1 = min(max(y1, 0), HH - 1);

    Samp s;
    s.o0 = (cy0 * WW + cx0) * CC;  s.w0 = wx0 * wy0 * ((vx0 && vy0) ? 1.0f : 0.0f);
    s.o1 = (cy0 * WW + cx1) * CC;  s.w1 = wx1 * wy0 * ((vx1 && vy0) ? 1.0f : 0.0f);
    s.o2 = (cy1 * WW + cx0) * CC;  s.w2 = wx0 * wy1 * ((vx0 && vy1) ? 1.0f : 0.0f);
    s.o3 = (cy1 * WW + cx1) * CC;  s.w3 = wx1 * wy1 * ((vx1 && vy1) ? 1.0f : 0.0f);
    return s;
}

__device__ __forceinline__ float4 samp4(const float* __restrict__ base,
                                        const Samp& s, int q) {
    const float4* p0 = reinterpret_cast<const float4*>(base + s.o0) + q;
    const float4* p1 = reinterpret_cast<const float4*>(base + s.o1) + q;
    const float4* p2 = reinterpret_cast<const float4*>(base + s.o2) + q;
    const float4* p3 = reinterpret_cast<const float4*>(base + s.o3) + q;
    float4 a = __ldg(p0), b = __ldg(p1), c = __ldg(p2), d = __ldg(p3);
    float4 r;
    r.x = a.x * s.w0 + b.x * s.w1 + c.x * s.w2 + d.x * s.w3;
    r.y = a.y * s.w0 + b.y * s.w1 + c.y * s.w2 + d.y * s.w3;
    r.z = a.z * s.w0 + b.z * s.w1 + c.z * s.w2 + d.z * s.w3;
    r.w = a.w * s.w0 + b.w * s.w1 + c.w * s.w2 + d.w * s.w3;
    return r;
}

__global__ void __launch_bounds__(128)
fgf_main(const float* __restrict__ pts,
         const float* __restrict__ Kmat,
         const float* __restrict__ Emat,
         float* __restrict__ out) {
    int n  = blockIdx.x * blockDim.x + threadIdx.x;
    int bv = blockIdx.y;
    if (n >= NN) return;
    int b = bv / VV;

    const float* Kp = Kmat + bv * 9;
    const float* Ep = Emat + bv * 12;

    float px = pts[((size_t)b * 3 + 0) * NN + n];
    float py = pts[((size_t)b * 3 + 1) * NN + n];
    float pz = pts[((size_t)b * 3 + 2) * NN + n];

    float tx = Ep[0] * px + Ep[1] * py + Ep[2]  * pz + Ep[3];
    float ty = Ep[4] * px + Ep[5] * py + Ep[6]  * pz + Ep[7];
    float tz = Ep[8] * px + Ep[9] * py + Ep[10] * pz + Ep[11];

    float inz = 1.0f / tz;
    float nx = tx * inz, ny = ty * inz;
    float u = Kp[0] * nx + Kp[1] * ny + Kp[2];
    float v = Kp[3] * nx + Kp[4] * ny + Kp[5];

    const float sx = 2.0f / (float)(WW - 1);
    const float sy = 2.0f / (float)(HH - 1);
    float gx = (u - 0.5f) * sx - 1.0f;
    float gy = (v - 0.5f) * sy - 1.0f;
    const float dx = sx, dy = sy;

    Samp sc = make_samp(gx,      gy);
    Samp sl = make_samp(gx - dx, gy);
    Samp sr = make_samp(gx + dx, gy);
    Samp st = make_samp(gx,      gy - dy);
    Samp sb = make_samp(gx,      gy + dy);

    const float* base = g_fmT + (size_t)bv * HW * CC;
    float*  fout = out;
    float2* gout = reinterpret_cast<float2*>(out + (size_t)BV * CC * NN);

#pragma unroll
    for (int q = 0; q < 4; q++) {
        float4 fc = samp4(base, sc, q);
        float4 fl = samp4(base, sl, q);
        float4 fr = samp4(base, sr, q);
        float4 ft = samp4(base, st, q);
        float4 fb = samp4(base, sb, q);

        int c = 4 * q;
        size_t fo = ((size_t)bv * CC + c) * NN + n;

        fout[fo]          = fc.x;
        fout[fo + NN]     = fc.y;
        fout[fo + 2*NN]   = fc.z;
        fout[fo + 3*NN]   = fc.w;

        gout[fo]        = make_float2(0.5f * (fr.x - fl.x), 0.5f * (fb.x - ft.x));
        gout[fo + NN]   = make_float2(0.5f * (fr.y - fl.y), 0.5f * (fb.y - ft.y));
        gout[fo + 2*NN] = make_float2(0.5f * (fr.z - fl.z), 0.5f * (fb.z - ft.z));
        gout[fo + 3*NN] = make_float2(0.5f * (fr.w - fl.w), 0.5f * (fb.w - ft.w));
    }
}

// ---------------------------------------------------------------------------
// Launch
// ---------------------------------------------------------------------------
extern "C" void kernel_launch(void* const* d_in, const int* in_sizes, int n_in,
                              void* d_out, int out_size) {
    const float* fm  = (const float*)d_in[0];  // (B,V,C,H,W)
    const float* pts = (const float*)d_in[1];  // (B,3,N)
    const float* Km  = (const float*)d_in[2];  // (B,V,3,3)
    const float* Em  = (const float*)d_in[3];  // (B,V,3,4)
    float* out = (float*)d_out;                // f (B,V,C,N) then f_grad (B,V,C,N,2)

    {
        int total = BV * HW;
        int threads = 256;
        int blocks = (total + threads - 1) / threads;
        fgf_transpose<<<blocks, threads>>>(fm);
    }
    {
        dim3 block(128);
        dim3 grid((NN + 127) / 128, BV);
        fgf_main<<<grid, block>>>(pts, Km, Em, out);
    }
}

// round 2
// speedup vs baseline: 1.9217x; 1.9217x over previous
#include <cuda_runtime.h>
#include <cstdint>

#define BB 2
#define VV 5
#define CC 16
#define HH 512
#define WW 640
#define NN 131072
#define BV (BB*VV)
#define HW (HH*WW)

// Transposed feature maps: (BV, H, W, C) — all 16 channels of a pixel contiguous (64B).
__device__ float g_fmT[(size_t)BV * HW * CC];

// ---------------------------------------------------------------------------
// Kernel 1: transpose (BV, C, H, W) -> (BV, H, W, C)
// ---------------------------------------------------------------------------
__global__ void fgf_transpose(const float* __restrict__ fm) {
    int pix = blockIdx.x * blockDim.x + threadIdx.x;
    if (pix >= BV * HW) return;
    int bv = pix / HW;
    int r  = pix - bv * HW;
    const float* src = fm + (size_t)bv * CC * HW + r;
    float v[CC];
#pragma unroll
    for (int c = 0; c < CC; c++) v[c] = src[(size_t)c * HW];
    float4* dst = reinterpret_cast<float4*>(g_fmT + ((size_t)bv * HW + r) * CC);
#pragma unroll
    for (int q = 0; q < 4; q++)
        dst[q] = make_float4(v[4*q], v[4*q+1], v[4*q+2], v[4*q+3]);
}

// ---------------------------------------------------------------------------
// Kernel 2: project + 5-point stencil bilinear sampling on a shared 12-tap cross
// Block = 128 threads = 32 points x 4 channel-quad lanes.
// ---------------------------------------------------------------------------
__device__ __forceinline__ float4 lerp2d(float4 p00, float4 p10, float4 p01, float4 p11,
                                         float fx, float fy) {
    float w00 = (1.0f - fx) * (1.0f - fy);
    float w10 = fx * (1.0f - fy);
    float w01 = (1.0f - fx) * fy;
    float w11 = fx * fy;
    float4 r;
    r.x = p00.x * w00 + p10.x * w10 + p01.x * w01 + p11.x * w11;
    r.y = p00.y * w00 + p10.y * w10 + p01.y * w01 + p11.y * w11;
    r.z = p00.z * w00 + p10.z * w10 + p01.z * w01 + p11.z * w11;
    r.w = p00.w * w00 + p10.w * w10 + p01.w * w01 + p11.w * w11;
    return r;
}

__global__ void __launch_bounds__(128)
fgf_main(const float* __restrict__ pts,
         const float* __restrict__ Kmat,
         const float* __restrict__ Emat,
         float* __restrict__ out) {
    __shared__ float  sf[CC][34];   // pad 34 -> conflict-free quad writes
    __shared__ float2 sg[CC][34];

    int tid = threadIdx.x;
    int p   = tid >> 2;        // point within block (0..31)
    int q   = tid & 3;         // channel quad (0..3)
    int bv  = blockIdx.y;
    int b   = bv / VV;
    int n   = blockIdx.x * 32 + p;

    const float* Kp = Kmat + bv * 9;
    const float* Ep = Emat + bv * 12;

    float px = pts[((size_t)b * 3 + 0) * NN + n];
    float py = pts[((size_t)b * 3 + 1) * NN + n];
    float pz = pts[((size_t)b * 3 + 2) * NN + n];

    float tx = Ep[0] * px + Ep[1] * py + Ep[2]  * pz + Ep[3];
    float ty = Ep[4] * px + Ep[5] * py + Ep[6]  * pz + Ep[7];
    float tz = Ep[8] * px + Ep[9] * py + Ep[10] * pz + Ep[11];

    float inz = 1.0f / tz;
    float nx = tx * inz, ny = ty * inz;
    float u = Kp[0] * nx + Kp[1] * ny + Kp[2];
    float v = Kp[3] * nx + Kp[4] * ny + Kp[5];

    const float sx = 2.0f / (float)(WW - 1);
    const float sy = 2.0f / (float)(HH - 1);
    float gx = (u - 0.5f) * sx - 1.0f;
    float gy = (v - 0.5f) * sy - 1.0f;

    // Pixel-space coords for all 5 stencil samples (mirror reference arithmetic)
    float ix  = ((gx + 1.0f)      * (float)WW - 1.0f) * 0.5f;
    float iy  = ((gy + 1.0f)      * (float)HH - 1.0f) * 0.5f;
    float ixl = ((gx - sx + 1.0f) * (float)WW - 1.0f) * 0.5f;
    float ixr = ((gx + sx + 1.0f) * (float)WW - 1.0f) * 0.5f;
    float iyt = ((gy - sy + 1.0f) * (float)HH - 1.0f) * 0.5f;
    float iyb = ((gy + sy + 1.0f) * (float)HH - 1.0f) * 0.5f;

    float x0f = floorf(ix), y0f = floorf(iy);
    int x0 = (int)x0f, y0 = (int)y0f;

    float fa  = ix  - x0f;           // center x frac (taps x0, x0+1)
    float fb  = iy  - y0f;           // center y frac (taps y0, y0+1)
    float fxl = ixl - x0f + 1.0f;    // left  sample frac rel. x0-1
    float fxr = ixr - x0f - 1.0f;    // right sample frac rel. x0+1
    float fyt = iyt - y0f + 1.0f;    // top    sample frac rel. y0-1
    float fyb = iyb - y0f - 1.0f;    // bottom sample frac rel. y0+1

    // Defensive clamps (all interior for this problem's inputs)
    int cxm = max(x0 - 1, 0);
    int cx0 = min(max(x0,     0), WW - 1);
    int cx1 = min(max(x0 + 1, 0), WW - 1);
    int cx2 = min(x0 + 2, WW - 1);
    int rym = max(y0 - 1, 0);
    int ry0 = min(max(y0,     0), HH - 1);
    int ry1 = min(max(y0 + 1, 0), HH - 1);
    int ry2 = min(y0 + 2, HH - 1);

    const float4* base4 = reinterpret_cast<const float4*>(g_fmT) + (size_t)bv * HW * 4;
    // 12 unique taps: 4 lanes of a point read consecutive float4s of the 64B pixel.
#define TAP(Y, X) __ldg(base4 + (((Y) * WW + (X)) * 4 + q))
    float4 A0 = TAP(ry0, cxm), A1 = TAP(ry0, cx0), A2 = TAP(ry0, cx1), A3 = TAP(ry0, cx2);
    float4 B0 = TAP(ry1, cxm), B1 = TAP(ry1, cx0), B2 = TAP(ry1, cx1), B3 = TAP(ry1, cx2);
    float4 T1 = TAP(rym, cx0), T2 = TAP(rym, cx1);
    float4 U1 = TAP(ry2, cx0), U2 = TAP(ry2, cx1);
#undef TAP

    float4 fC = lerp2d(A1, A2, B1, B2, fa,  fb);
    float4 fL = lerp2d(A0, A1, B0, B1, fxl, fb);
    float4 fR = lerp2d(A2, A3, B2, B3, fxr, fb);
    float4 fT = lerp2d(T1, T2, A1, A2, fa,  fyt);
    float4 fB = lerp2d(B1, B2, U1, U2, fa,  fyb);

    int c0 = 4 * q;
    sf[c0 + 0][p] = fC.x;  sg[c0 + 0][p] = make_float2(0.5f*(fR.x - fL.x), 0.5f*(fB.x - fT.x));
    sf[c0 + 1][p] = fC.y;  sg[c0 + 1][p] = make_float2(0.5f*(fR.y - fL.y), 0.5f*(fB.y - fT.y));
    sf[c0 + 2][p] = fC.z;  sg[c0 + 2][p] = make_float2(0.5f*(fR.z - fL.z), 0.5f*(fB.z - fT.z));
    sf[c0 + 3][p] = fC.w;  sg[c0 + 3][p] = make_float2(0.5f*(fR.w - fL.w), 0.5f*(fB.w - fT.w));

    __syncthreads();

    // Coalesced writes: 4 iterations, each warp writes 32 consecutive n for one channel
    float*  fout = out;
    float2* gout = reinterpret_cast<float2*>(out + (size_t)BV * CC * NN);
    int wp = tid & 31;
    int cb = tid >> 5;          // 0..3
    size_t nb = (size_t)blockIdx.x * 32 + wp;
#pragma unroll
    for (int it = 0; it < 4; it++) {
        int c = it * 4 + cb;
        size_t o = ((size_t)bv * CC + c) * NN + nb;
        fout[o] = sf[c][wp];
        gout[o] = sg[c][wp];
    }
}

// ---------------------------------------------------------------------------
extern "C" void kernel_launch(void* const* d_in, const int* in_sizes, int n_in,
                              void* d_out, int out_size) {
    const float* fm  = (const float*)d_in[0];  // (B,V,C,H,W)
    const float* pts = (const float*)d_in[1];  // (B,3,N)
    const float* Km  = (const float*)d_in[2];  // (B,V,3,3)
    const float* Em  = (const float*)d_in[3];  // (B,V,3,4)
    float* out = (float*)d_out;                // f (B,V,C,N) ++ f_grad (B,V,C,N,2)

    {
        int total = BV * HW;
        int threads = 256;
        fgf_transpose<<<(total + threads - 1) / threads, threads>>>(fm);
    }
    {
        dim3 grid(NN / 32, BV);
        fgf_main<<<grid, 128>>>(pts, Km, Em, out);
    }
}